// round 4
// baseline (speedup 1.0000x reference)
#include <cuda_runtime.h>
#include <cstdint>

// FixedGaussianBlur: depthwise 21x21 Gaussian (sigma=3), reflect padding,
// x[32,3,512,512] f32 -> y[32,3,512,512] f32.
// Separable, fused. 64x64 tile, halo 10.
// Input tile stored ROW-PAIR INTERLEAVED (s2[rp][c] = (x[2rp][c], x[2rp+1][c]))
// so the horizontal pass runs entirely on fma.rn.f32x2 (2 rows per op).
// Horizontal writes row-major s_h (stride 66); vertical pass is col-pair f32x2.

#define IMG_W 512
#define IMG_H 512
#define PAD 10
#define KS 21
#define TW 64
#define TH 64
#define NTHREADS 512
#define NIMG 96

#define S2_ROWS 42          // row pairs (84 rows)
#define S2_COLS 84
#define S2_W 85             // u64 stride
#define SH_ROWS 84
#define SH_W 66             // float stride (even: keeps LDS.64 aligned)

#define SMEM_S2_BYTES (S2_ROWS * S2_W * 8)            // 28560
#define SMEM_SH_BYTES (SH_ROWS * SH_W * 4)            // 22176
#define SMEM_TOTAL (SMEM_S2_BYTES + SMEM_SH_BYTES)    // 50736

#define W0  0.13303900f
#define W1  0.12584950f
#define W2  0.10652928f
#define W3  0.08069223f
#define W4  0.05469397f
#define W5  0.03317359f
#define W6  0.01800488f
#define W7  0.00874446f
#define W8  0.00380033f
#define W9  0.00147793f
#define W10 0.00051432f

__device__ __forceinline__ float tap(int j) {
    constexpr float w[KS] = {W10, W9, W8, W7, W6, W5, W4, W3, W2, W1, W0,
                             W1, W2, W3, W4, W5, W6, W7, W8, W9, W10};
    return w[j];
}

__device__ __forceinline__ int reflect_idx(int i, int n) {
    i = (i < 0) ? -i : i;
    i = (i >= n) ? (2 * n - 2 - i) : i;
    return i;
}

__device__ __forceinline__ uint64_t bcast2(float f) {
    uint32_t b = __float_as_uint(f);
    return ((uint64_t)b << 32) | (uint64_t)b;
}

__device__ __forceinline__ uint64_t pack2(float lo, float hi) {
    return ((uint64_t)__float_as_uint(hi) << 32) | (uint64_t)__float_as_uint(lo);
}

__device__ __forceinline__ void ffma2(uint64_t& d, uint64_t a, uint64_t b, uint64_t c) {
    asm("fma.rn.f32x2 %0, %1, %2, %3;" : "=l"(d) : "l"(a), "l"(b), "l"(c));
}

__global__ __launch_bounds__(NTHREADS, 3)
void gauss_blur_fused(const float* __restrict__ in, float* __restrict__ out) {
    extern __shared__ __align__(16) char smem_raw[];
    uint64_t* s2 = reinterpret_cast<uint64_t*>(smem_raw);                  // [42][85]
    float* s_h = reinterpret_cast<float*>(smem_raw + SMEM_S2_BYTES);      // [84][66]

    const int tid = threadIdx.x;
    const int x0 = blockIdx.x * TW;
    const int y0 = blockIdx.y * TH;
    const float* __restrict__ base = in + (size_t)blockIdx.z * (IMG_W * IMG_H);

    // ---- Load 84x84 tile into row-pair interleaved layout ----
    const bool interior = (x0 >= PAD) && (x0 + TW + PAD <= IMG_W) &&
                          (y0 >= PAD) && (y0 + TH + PAD <= IMG_H);
    if (interior) {
        // units: 42 row-pairs x 42 col-pairs = 1764; thread does <=4
        int rp = tid / 42;
        int c2 = tid - rp * 42;
        const float* gb = base + (size_t)(y0 - PAD) * IMG_W + (x0 - PAD);
        #pragma unroll
        for (int it = 0; it < 4; ++it) {
            if (rp < S2_ROWS) {
                float2 a = __ldg((const float2*)(gb + (size_t)(2 * rp) * IMG_W + 2 * c2));
                float2 b = __ldg((const float2*)(gb + (size_t)(2 * rp + 1) * IMG_W + 2 * c2));
                s2[rp * S2_W + 2 * c2 + 0] = pack2(a.x, b.x);
                s2[rp * S2_W + 2 * c2 + 1] = pack2(a.y, b.y);
            }
            // advance 512 units: 512 = 12*42 + 8
            c2 += 8; rp += 12;
            if (c2 >= 42) { c2 -= 42; rp += 1; }
        }
    } else {
        // units: 42 row-pairs x 84 cols = 3528; thread does <=7
        int rp = tid / 84;
        int c = tid - rp * 84;
        #pragma unroll
        for (int it = 0; it < 7; ++it) {
            if (rp < S2_ROWS) {
                int gy0 = reflect_idx(y0 - PAD + 2 * rp, IMG_H);
                int gy1 = reflect_idx(y0 - PAD + 2 * rp + 1, IMG_H);
                int gx = reflect_idx(x0 - PAD + c, IMG_W);
                float a = __ldg(base + (size_t)gy0 * IMG_W + gx);
                float b = __ldg(base + (size_t)gy1 * IMG_W + gx);
                s2[rp * S2_W + c] = pack2(a, b);
            }
            // advance 512 units: 512 = 6*84 + 8
            c += 8; rp += 6;
            if (c >= 84) { c -= 84; rp += 1; }
        }
    }
    __syncthreads();

    // ---- Horizontal pass (packed over row pairs): 42 rp x 8 segs of 8 cols ----
    if (tid < S2_ROWS * 8) {              // 336 threads
        const int rp = tid >> 3;
        const int c0 = (tid & 7) << 3;    // output col base 0..56

        uint64_t acc2[8];
        #pragma unroll
        for (int c = 0; c < 8; ++c) acc2[c] = 0;

        const uint64_t* row = s2 + rp * S2_W + c0;
        #pragma unroll
        for (int k = 0; k < 28; ++k) {
            uint64_t v2 = row[k];
            #pragma unroll
            for (int c = 0; c < 8; ++c) {
                int j = k - c;
                if (j >= 0 && j < KS) ffma2(acc2[c], v2, bcast2(tap(j)), acc2[c]);
            }
        }

        float* h0 = s_h + (2 * rp) * SH_W + c0;
        float* h1 = s_h + (2 * rp + 1) * SH_W + c0;
        #pragma unroll
        for (int c = 0; c < 8; ++c) {
            h0[c] = __uint_as_float((uint32_t)acc2[c]);
            h1[c] = __uint_as_float((uint32_t)(acc2[c] >> 32));
        }
    }
    __syncthreads();

    // ---- Vertical pass (packed over col pairs): 32 cp x 16 groups of 4 rows ----
    {
        const int cp = tid & 31;           // cols 2cp, 2cp+1
        const int g = (tid >> 5) << 2;     // first output row 0,4,...,60

        uint64_t acc[4] = {0, 0, 0, 0};
        const float* col = s_h + 2 * cp;

        #pragma unroll
        for (int t = 0; t < 24; ++t) {
            uint64_t v2 = *reinterpret_cast<const uint64_t*>(col + (g + t) * SH_W);
            #pragma unroll
            for (int o = 0; o < 4; ++o) {
                int j = t - o;
                if (j >= 0 && j < KS) {
                    int wi = (j <= 10) ? j : (20 - j);
                    ffma2(acc[o], v2, bcast2(tap(wi)), acc[o]);
                }
            }
        }

        char* dst = (char*)(out + (size_t)blockIdx.z * (IMG_W * IMG_H)
                                + (size_t)(y0 + g) * IMG_W + (x0 + 2 * cp));
        #pragma unroll
        for (int o = 0; o < 4; ++o)
            *reinterpret_cast<uint64_t*>(dst + (size_t)o * IMG_W * 4) = acc[o];
    }
}

extern "C" void kernel_launch(void* const* d_in, const int* in_sizes, int n_in,
                              void* d_out, int out_size) {
    (void)in_sizes; (void)n_in; (void)out_size;
    const float* x = (const float*)d_in[0];
    float* y = (float*)d_out;
    cudaFuncSetAttribute(gauss_blur_fused,
                         cudaFuncAttributeMaxDynamicSharedMemorySize, SMEM_TOTAL);
    dim3 grid(IMG_W / TW, IMG_H / TH, NIMG);  // 8 x 8 x 96
    gauss_blur_fused<<<grid, NTHREADS, SMEM_TOTAL>>>(x, y);
}

// round 5
// speedup vs baseline: 1.5047x; 1.5047x over previous
#include <cuda_runtime.h>
#include <cstdint>

// FixedGaussianBlur: depthwise 21x21 Gaussian (sigma=3), reflect padding,
// x[32,3,512,512] f32 -> y[32,3,512,512] f32.
// Separable, fused, in-place smem tile. TW=64, TH=128 -> 64x148 halo tile.
// Horizontal: scalar FFMA-imm, in place, 2 phases (rows 0..127 / 128..147).
// Vertical: packed fma.rn.f32x2 over col pairs, 8-row groups (conflict-free).

#define IMG_W 512
#define IMG_H 512
#define PAD 10
#define KS 21
#define TW 64
#define TH 128
#define SROWS 148          // TH + 2*PAD
#define SCOLS 84           // TW + 2*PAD
#define NTHREADS 512
#define NIMG 96
#define NU64 (SROWS * SCOLS / 2)   // 6216 u64 tile words
#define SMEM_BYTES (SROWS * SCOLS * 4)  // 49728

#define W0  0.13303900f
#define W1  0.12584950f
#define W2  0.10652928f
#define W3  0.08069223f
#define W4  0.05469397f
#define W5  0.03317359f
#define W6  0.01800488f
#define W7  0.00874446f
#define W8  0.00380033f
#define W9  0.00147793f
#define W10 0.00051432f

__device__ __forceinline__ float tap(int j) {
    constexpr float w[KS] = {W10, W9, W8, W7, W6, W5, W4, W3, W2, W1, W0,
                             W1, W2, W3, W4, W5, W6, W7, W8, W9, W10};
    return w[j];
}

__device__ __forceinline__ int reflect_idx(int i, int n) {
    i = (i < 0) ? -i : i;
    i = (i >= n) ? (2 * n - 2 - i) : i;
    return i;
}

__device__ __forceinline__ uint64_t bcast2(float f) {
    uint32_t b = __float_as_uint(f);
    return ((uint64_t)b << 32) | (uint64_t)b;
}

__device__ __forceinline__ void ffma2(uint64_t& d, uint64_t a, uint64_t b, uint64_t c) {
    asm("fma.rn.f32x2 %0, %1, %2, %3;" : "=l"(d) : "l"(a), "l"(b), "l"(c));
}

// 16-output horizontal filter on one row segment: reads s[row][seg..seg+35],
// returns outputs in o[16] (caller stores after barrier).
__device__ __forceinline__ void hfilter16(const float* srow, float o[16]) {
    float v[36];
    const float4* p = reinterpret_cast<const float4*>(srow);
    #pragma unroll
    for (int q = 0; q < 9; ++q) {
        float4 t = p[q];
        v[4 * q + 0] = t.x; v[4 * q + 1] = t.y;
        v[4 * q + 2] = t.z; v[4 * q + 3] = t.w;
    }
    #pragma unroll
    for (int c = 0; c < 16; ++c) {
        float acc = v[c] * tap(0);
        #pragma unroll
        for (int j = 1; j < KS; ++j) acc = fmaf(v[c + j], tap(j), acc);
        o[c] = acc;
    }
}

__global__ __launch_bounds__(NTHREADS, 3)
void gauss_blur_fused(const float* __restrict__ in, float* __restrict__ out) {
    extern __shared__ __align__(16) float s[];   // [SROWS][SCOLS] row-major

    const int tid = threadIdx.x;
    const int x0 = blockIdx.x * TW;
    const int y0 = blockIdx.y * TH;
    const float* __restrict__ base = in + (size_t)blockIdx.z * (IMG_W * IMG_H);

    // ---- Load 148x84 tile ----
    const bool x_int = (x0 >= PAD) && (x0 + TW + PAD <= IMG_W);
    if (x_int) {
        // vectorized: 6216 LDG.64 (8B aligned: x0-10 even), rows reflected
        int idx = tid;
        #pragma unroll
        for (int it = 0; it < (NU64 + NTHREADS - 1) / NTHREADS; ++it) {
            if (idx < NU64) {
                int r = idx / (SCOLS / 2);
                int c2 = idx - r * (SCOLS / 2);
                int gy = reflect_idx(y0 - PAD + r, IMG_H);
                uint64_t v = __ldg((const uint64_t*)(base + (size_t)gy * IMG_W
                                                     + (x0 - PAD) + 2 * c2));
                *reinterpret_cast<uint64_t*>(&s[r * SCOLS + 2 * c2]) = v;
            }
            idx += NTHREADS;
        }
    } else {
        int idx = tid;
        #pragma unroll
        for (int it = 0; it < (SROWS * SCOLS + NTHREADS - 1) / NTHREADS; ++it) {
            if (idx < SROWS * SCOLS) {
                int r = idx / SCOLS;
                int c = idx - r * SCOLS;
                int gy = reflect_idx(y0 - PAD + r, IMG_H);
                int gx = reflect_idx(x0 - PAD + c, IMG_W);
                s[r * SCOLS + c] = __ldg(base + (size_t)gy * IMG_W + gx);
            }
            idx += NTHREADS;
        }
    }
    __syncthreads();

    // ---- Horizontal pass, in place: 148 rows x 4 segs of 16 = 592 units ----
    // Phase 1: units 0..511 (rows 0..127). Phase 2: units 512..591 (rows 128..147).
    {
        const int row1 = tid >> 2;
        const int seg1 = (tid & 3) << 4;
        float o1[16];
        hfilter16(&s[row1 * SCOLS + seg1], o1);
        __syncthreads();   // all phase-1 reads done
        {
            float4* q = reinterpret_cast<float4*>(&s[row1 * SCOLS + seg1]);
            #pragma unroll
            for (int k = 0; k < 4; ++k)
                q[k] = make_float4(o1[4 * k], o1[4 * k + 1], o1[4 * k + 2], o1[4 * k + 3]);
        }
        // Phase 2: rows 128..147 are untouched by phase-1 writes (rows 0..127)
        const bool p2 = (tid < 592 - NTHREADS);   // 80 threads
        const int u2 = tid + NTHREADS;
        const int row2 = u2 >> 2;
        const int seg2 = (u2 & 3) << 4;
        float o2[16];
        if (p2) hfilter16(&s[row2 * SCOLS + seg2], o2);
        __syncthreads();   // phase-2 reads done (and phase-1 writes visible)
        if (p2) {
            float4* q = reinterpret_cast<float4*>(&s[row2 * SCOLS + seg2]);
            #pragma unroll
            for (int k = 0; k < 4; ++k)
                q[k] = make_float4(o2[4 * k], o2[4 * k + 1], o2[4 * k + 2], o2[4 * k + 3]);
        }
    }
    __syncthreads();

    // ---- Vertical pass: 32 col-pairs x 16 groups of 8 rows = 512 threads ----
    {
        const int cp = tid & 31;            // cols 2cp, 2cp+1
        const int g = (tid >> 5) << 3;      // first output row: 0,8,...,120

        uint64_t acc[8];
        #pragma unroll
        for (int o = 0; o < 8; ++o) acc[o] = 0;

        const float* col = s + 2 * cp;
        #pragma unroll
        for (int t = 0; t < 28; ++t) {
            uint64_t v2 = *reinterpret_cast<const uint64_t*>(col + (g + t) * SCOLS);
            #pragma unroll
            for (int o = 0; o < 8; ++o) {
                int j = t - o;
                if (j >= 0 && j < KS) {
                    int wi = (j <= 10) ? j : (20 - j);
                    ffma2(acc[o], v2, bcast2(tap(wi)), acc[o]);
                }
            }
        }

        char* dst = (char*)(out + (size_t)blockIdx.z * (IMG_W * IMG_H)
                                + (size_t)(y0 + g) * IMG_W + (x0 + 2 * cp));
        #pragma unroll
        for (int o = 0; o < 8; ++o)
            *reinterpret_cast<uint64_t*>(dst + (size_t)o * IMG_W * 4) = acc[o];
    }
}

extern "C" void kernel_launch(void* const* d_in, const int* in_sizes, int n_in,
                              void* d_out, int out_size) {
    (void)in_sizes; (void)n_in; (void)out_size;
    const float* x = (const float*)d_in[0];
    float* y = (float*)d_out;
    cudaFuncSetAttribute(gauss_blur_fused,
                         cudaFuncAttributeMaxDynamicSharedMemorySize, SMEM_BYTES);
    dim3 grid(IMG_W / TW, IMG_H / TH, NIMG);  // 8 x 4 x 96
    gauss_blur_fused<<<grid, NTHREADS, SMEM_BYTES>>>(x, y);
}